// round 16
// baseline (speedup 1.0000x reference)
#include <cuda_runtime.h>
#include <cstdint>
#include <cmath>

// ---------------------------------------------------------------------------
// Problem constants
// ---------------------------------------------------------------------------
#define VOCAB     10000
#define NDEM      2
#define EMB       128
#define B_ROWS    16384
#define SRC_COLS  10002
#define NH        16
#define KPAD      10240
#define KSPLIT    8
#define KRANGE    (KPAD / KSPLIT)    // 1280
#define KT        64                 // k-columns per pipeline tile
#define NT        (KRANGE / KT)      // 20
#define NG        16                 // 4-col groups per tile
#define TM        256                // rows per CTA (1 row per thread)
#define THREADS   256
#define NCTA      ((B_ROWS / TM) * KSPLIT)   // 512 -> single wave at occ 4
#define EST       88                 // 22-word stride: all 16 entries on
                                     // distinct banks (22m mod 32 distinct)

// Scratch (__device__ globals: allocation-free rule)
__device__ float g_EW1[KPAD * NH];            // [vocab-col][16]
__device__ float g_S[KSPLIT * 17 * B_ROWS];   // 8 partials x (16 sums + count)

// ---------------------------------------------------------------------------
// helpers
// ---------------------------------------------------------------------------
__device__ __forceinline__ void fma2(unsigned long long& d, unsigned long long a,
                                     unsigned long long b) {
    asm("fma.rn.f32x2 %0, %1, %2, %0;" : "+l"(d) : "l"(a), "l"(b));
}
__device__ __forceinline__ unsigned long long pack2(float lo, float hi) {
    unsigned long long r;
    asm("mov.b64 %0, {%1, %2};" : "=l"(r) : "r"(__float_as_uint(lo)), "r"(__float_as_uint(hi)));
    return r;
}
__device__ __forceinline__ void cp16(void* s, const void* g) {
    unsigned sa = (unsigned)__cvta_generic_to_shared(s);
    asm volatile("cp.async.cg.shared.global [%0], [%1], 16;" :: "r"(sa), "l"(g));
}
// consume one 4-col group for this thread's row: conflict-free 8B lookups
__device__ __forceinline__ void consume_group(unsigned tbl, uint2 bw, int g, float* acc) {
    const unsigned m = ((bw.x >> (2 * g)) & 3u) | (((bw.y >> (2 * g)) & 3u) << 2);
    const unsigned a = tbl + (g * 16 + m) * EST;
    float x0, x1, x2, x3;
    asm("ld.shared.v2.f32 {%0,%1}, [%2];"    : "=f"(x0), "=f"(x1) : "r"(a));
    asm("ld.shared.v2.f32 {%0,%1}, [%2+8];"  : "=f"(x2), "=f"(x3) : "r"(a));
    acc[0] += x0; acc[1] += x1; acc[2] += x2; acc[3] += x3;
    asm("ld.shared.v2.f32 {%0,%1}, [%2+16];" : "=f"(x0), "=f"(x1) : "r"(a));
    asm("ld.shared.v2.f32 {%0,%1}, [%2+24];" : "=f"(x2), "=f"(x3) : "r"(a));
    acc[4] += x0; acc[5] += x1; acc[6] += x2; acc[7] += x3;
    asm("ld.shared.v2.f32 {%0,%1}, [%2+32];" : "=f"(x0), "=f"(x1) : "r"(a));
    asm("ld.shared.v2.f32 {%0,%1}, [%2+40];" : "=f"(x2), "=f"(x3) : "r"(a));
    acc[8]  += x0; acc[9]  += x1; acc[10] += x2; acc[11] += x3;
    asm("ld.shared.v2.f32 {%0,%1}, [%2+48];" : "=f"(x0), "=f"(x1) : "r"(a));
    asm("ld.shared.v2.f32 {%0,%1}, [%2+56];" : "=f"(x2), "=f"(x3) : "r"(a));
    acc[12] += x0; acc[13] += x1; acc[14] += x2; acc[15] += x3;
}

// ---------------------------------------------------------------------------
// Kernel 0: g_EW1[c][n] = sum_d embed[c][d] * W1[(2+d)*16+n]   (0 for c>=VOCAB)
// ---------------------------------------------------------------------------
__global__ __launch_bounds__(512) void ew1_kernel(const float* __restrict__ embed,
                                                  const float* __restrict__ W1) {
    __shared__ float sh_emb[32][EMB];
    __shared__ float sh_w1[EMB][NH];
    const int tid = threadIdx.x;
    const int c0  = blockIdx.x * 32;

    for (int i = tid; i < EMB * NH; i += 512)
        sh_w1[i >> 4][i & 15] = W1[NDEM * NH + i];
    for (int i = tid; i < 32 * EMB; i += 512) {
        int r = i >> 7, k = c0 + r;
        sh_emb[r][i & 127] = (k < VOCAB) ? embed[(long long)k * EMB + (i & 127)] : 0.f;
    }
    __syncthreads();

    const int r = tid >> 4, n = tid & 15, k = c0 + r;
    float a0 = 0.f, a1 = 0.f;
    #pragma unroll 16
    for (int d = 0; d < EMB; d += 2) {
        a0 += sh_emb[r][d]     * sh_w1[d][n];
        a1 += sh_emb[r][d + 1] * sh_w1[d + 1][n];
    }
    g_EW1[k * NH + n] = (k < VOCAB) ? (a0 + a1) : 0.f;
}

// ---------------------------------------------------------------------------
// Kernel 1: partial S = mask_tile @ EW1 via 4-bit subset-sum table.
//   R15 chassis; restructured schedule for continuous DRAM occupancy:
//     tile start: cp.async next e  +  issue 16 next-tile row loads
//     build table (overlaps the in-flight loads)  -> sync
//     consume groups 0..7  + ballot first 16 loads   (cover > 700 cyc)
//     issue second 16 loads
//     consume groups 8..15 + ballot second 16 loads
//   Bit layout: col k -> word (k&1), bit (k>>1). Nibble mapping (R9-proven).
// ---------------------------------------------------------------------------
__global__ __launch_bounds__(THREADS, 4) void pool_kernel(const float* __restrict__ src) {
    __shared__ __align__(16) float sh_tbl[NG * 16 * (EST / 4)];  // 22.5 KB
    __shared__ __align__(16) float sh_e[2][KT * NH];             // 8 KB
    __shared__ __align__(8)  uint2 sh_bits[2][TM];               // 4 KB

    const int tid  = threadIdx.x;
    const int w    = tid >> 5;
    const int lane = tid & 31;
    const int mtile = blockIdx.x >> 3;           // / KSPLIT
    const int part  = blockIdx.x & (KSPLIT - 1);
    const int row0  = mtile * TM;
    const int kbase = part * KRANGE;
    const float* sb = src + (long long)row0 * SRC_COLS + NDEM;
    const int cl = 2 * lane;                 // lane's (even) col offset in a tile
    const unsigned tbl = (unsigned)__cvta_generic_to_shared(&sh_tbl[0]);

    // this thread's table item: group bg, mask bm
    const int bg = tid >> 4, bm = tid & 15;
    const unsigned long long q0 = pack2((bm & 1) ? 1.f : 0.f, (bm & 1) ? 1.f : 0.f);  // e[4g]
    const unsigned long long q1 = pack2((bm & 2) ? 1.f : 0.f, (bm & 2) ? 1.f : 0.f);  // e[4g+2]
    const unsigned long long q2 = pack2((bm & 4) ? 1.f : 0.f, (bm & 4) ? 1.f : 0.f);  // e[4g+1]
    const unsigned long long q3 = pack2((bm & 8) ? 1.f : 0.f, (bm & 8) ? 1.f : 0.f);  // e[4g+3]
    const unsigned tdst = tbl + (bg * 16 + bm) * EST;

    // ---------------- prologue: stage tile 0 ----------------
    cp16(&sh_e[0][tid * 4], g_EW1 + kbase * NH + tid * 4);
    asm volatile("cp.async.commit_group;");
    {
        const int c = kbase + cl;
        #pragma unroll
        for (int bb = 0; bb < 4; ++bb) {
            float2 v[8];
            #pragma unroll
            for (int j = 0; j < 8; ++j) {
                int row = 32 * w + 8 * bb + j;
                v[j] = (c < VOCAB)
                     ? __ldcs(reinterpret_cast<const float2*>(sb + (long long)row * SRC_COLS + c))
                     : make_float2(0.f, 0.f);
            }
            #pragma unroll
            for (int j = 0; j < 8; ++j) {
                unsigned b0 = __ballot_sync(0xffffffffu, v[j].x != 0.f);
                unsigned b1 = __ballot_sync(0xffffffffu, v[j].y != 0.f);
                if (lane == 0) sh_bits[0][32 * w + 8 * bb + j] = make_uint2(b0, b1);
            }
        }
    }
    asm volatile("cp.async.wait_group 0;" ::: "memory");
    __syncthreads();

    float acc[16];
    #pragma unroll
    for (int i = 0; i < 16; ++i) acc[i] = 0.f;
    int cnt = 0;

    // ---------------- main loop ----------------
    for (int t = 0; t < NT; ++t) {
        const int buf = t & 1, nbuf = buf ^ 1;
        const bool stg = (t + 1 < NT);
        const int cnx = kbase + (t + 1) * KT + cl;

        // (1) prefetch next e-tile + issue FIRST 16 next-tile row loads
        if (stg) {
            cp16(&sh_e[nbuf][tid * 4], g_EW1 + (kbase + (t + 1) * KT) * NH + tid * 4);
            asm volatile("cp.async.commit_group;");
        }
        float2 v[16];
        if (stg) {
            #pragma unroll
            for (int j = 0; j < 16; ++j) {
                int row = 32 * w + j;
                v[j] = (cnx < VOCAB)
                     ? __ldcs(reinterpret_cast<const float2*>(sb + (long long)row * SRC_COLS + cnx))
                     : make_float2(0.f, 0.f);
            }
        }

        // (2) build subset-sum table from sh_e[buf] (overlaps the loads)
        {
            const unsigned eb = (unsigned)__cvta_generic_to_shared(&sh_e[buf][0]) + bg * 256;
            #pragma unroll
            for (int i = 0; i < 8; ++i) {
                unsigned long long e0, e1, e2, e3, s = 0ull;
                asm("ld.shared.b64 %0, [%1];"     : "=l"(e0) : "r"(eb + i * 8));
                asm("ld.shared.b64 %0, [%1+64];"  : "=l"(e1) : "r"(eb + i * 8));
                asm("ld.shared.b64 %0, [%1+128];" : "=l"(e2) : "r"(eb + i * 8));
                asm("ld.shared.b64 %0, [%1+192];" : "=l"(e3) : "r"(eb + i * 8));
                fma2(s, e0, q0);   // col 4g
                fma2(s, e2, q1);   // col 4g+2
                fma2(s, e1, q2);   // col 4g+1
                fma2(s, e3, q3);   // col 4g+3
                asm volatile("st.shared.b64 [%0], %1;" :: "r"(tdst + i * 8), "l"(s));
            }
        }
        __syncthreads();   // table ready

        const uint2 bw = sh_bits[buf][tid];
        cnt += __popc(bw.x) + __popc(bw.y);

        // (3) consume groups 0..7, ballot the first 16 loads
        #pragma unroll
        for (int h = 0; h < 2; ++h) {
            #pragma unroll
            for (int gg = 0; gg < 4; ++gg)
                consume_group(tbl, bw, 4 * h + gg, acc);
            if (stg) {
                #pragma unroll
                for (int j = 0; j < 8; ++j) {
                    unsigned p0 = __ballot_sync(0xffffffffu, v[8 * h + j].x != 0.f);
                    unsigned p1 = __ballot_sync(0xffffffffu, v[8 * h + j].y != 0.f);
                    if (lane == 0) sh_bits[nbuf][32 * w + 8 * h + j] = make_uint2(p0, p1);
                }
            }
        }
        // (4) issue SECOND 16 loads
        if (stg) {
            #pragma unroll
            for (int j = 0; j < 16; ++j) {
                int row = 32 * w + 16 + j;
                v[j] = (cnx < VOCAB)
                     ? __ldcs(reinterpret_cast<const float2*>(sb + (long long)row * SRC_COLS + cnx))
                     : make_float2(0.f, 0.f);
            }
        }
        // (5) consume groups 8..15, ballot the second 16 loads
        #pragma unroll
        for (int h = 0; h < 2; ++h) {
            #pragma unroll
            for (int gg = 0; gg < 4; ++gg)
                consume_group(tbl, bw, 8 + 4 * h + gg, acc);
            if (stg) {
                #pragma unroll
                for (int j = 0; j < 8; ++j) {
                    unsigned p0 = __ballot_sync(0xffffffffu, v[8 * h + j].x != 0.f);
                    unsigned p1 = __ballot_sync(0xffffffffu, v[8 * h + j].y != 0.f);
                    if (lane == 0) sh_bits[nbuf][32 * w + 16 + 8 * h + j] = make_uint2(p0, p1);
                }
            }
        }
        if (stg) asm volatile("cp.async.wait_group 0;" ::: "memory");
        __syncthreads();   // bits[nbuf] + e[nbuf] ready; table free to rebuild
    }

    // ---------------- write partials (column-major, coalesced) ----------------
    const int rg = row0 + tid;
    #pragma unroll
    for (int n = 0; n < 16; ++n)
        g_S[(part * 17 + n) * B_ROWS + rg] = acc[n];
    g_S[(part * 17 + 16) * B_ROWS + rg] = (float)cnt;
}

// ---------------------------------------------------------------------------
// Kernel 2: reduce K-split partials + MLP epilogue
// ---------------------------------------------------------------------------
__global__ void mlp_kernel(const float* __restrict__ src, const float* __restrict__ W1,
                           const float* __restrict__ b1, const float* __restrict__ W2,
                           const float* __restrict__ b2, float* __restrict__ out) {
    int r = blockIdx.x * blockDim.x + threadIdx.x;
    if (r >= B_ROWS) return;

    float s[17];
    #pragma unroll
    for (int n = 0; n < 17; ++n) s[n] = 0.f;
    #pragma unroll
    for (int p = 0; p < KSPLIT; ++p)
        #pragma unroll
        for (int n = 0; n < 17; ++n)
            s[n] += g_S[(p * 17 + n) * B_ROWS + r];

    const float inv = 1.f / s[16];
    const float d0 = src[(long long)r * SRC_COLS + 0];
    const float d1 = src[(long long)r * SRC_COLS + 1];

    float o0 = b2[0], o1 = b2[1];
    #pragma unroll
    for (int j = 0; j < NH; ++j) {
        float z = d0 * W1[j] + d1 * W1[NH + j] + s[j] * inv + b1[j];
        float h = tanhf(z);
        o0 += h * W2[2 * j + 0];
        o1 += h * W2[2 * j + 1];
    }
    out[2 * r + 0] = o0;
    out[2 * r + 1] = o1;
}

// ---------------------------------------------------------------------------
// Launch
// ---------------------------------------------------------------------------
extern "C" void kernel_launch(void* const* d_in, const int* in_sizes, int n_in,
                              void* d_out, int out_size) {
    int iSrc = 0, iEmb = 1, iW1 = 2, iB1 = 3, iW2 = 4, iB2 = 5;
    for (int i = 0; i < n_in; ++i) {
        int s = in_sizes[i];
        if      (s == B_ROWS * SRC_COLS)  iSrc = i;
        else if (s == VOCAB * EMB)        iEmb = i;
        else if (s == (NDEM + EMB) * NH)  iW1  = i;
        else if (s == NH)                 iB1  = i;
        else if (s == NH * 2)             iW2  = i;
        else if (s == 2)                  iB2  = i;
    }
    const float* src   = (const float*)d_in[iSrc];
    const float* embed = (const float*)d_in[iEmb];
    const float* W1    = (const float*)d_in[iW1];
    const float* b1    = (const float*)d_in[iB1];
    const float* W2    = (const float*)d_in[iW2];
    const float* b2    = (const float*)d_in[iB2];
    float* out = (float*)d_out;

    ew1_kernel<<<KPAD / 32, 512>>>(embed, W1);
    pool_kernel<<<NCTA, THREADS>>>(src);
    mlp_kernel<<<(B_ROWS + 255) / 256, 256>>>(src, W1, b1, W2, b2, out);
}

// round 17
// speedup vs baseline: 1.0735x; 1.0735x over previous
#include <cuda_runtime.h>
#include <cstdint>
#include <cmath>

// ---------------------------------------------------------------------------
// Problem constants
// ---------------------------------------------------------------------------
#define VOCAB     10000
#define NDEM      2
#define EMB       128
#define B_ROWS    16384
#define SRC_COLS  10002
#define NH        16
#define KPAD      10240
#define KSPLIT    8
#define KRANGE    (KPAD / KSPLIT)    // 1280
#define KT        64                 // k-columns per pipeline tile
#define NT        (KRANGE / KT)      // 20
#define NG        16                 // 4-col groups per tile
#define TM        256                // rows per CTA (1 row per thread)
#define THREADS   256
#define NCTA      ((B_ROWS / TM) * KSPLIT)   // 512 -> single wave at occ 4
#define EST       88                 // 22-word stride: all 16 entries on
                                     // distinct banks (22m mod 32 distinct)

// Scratch (__device__ globals: allocation-free rule)
__device__ float g_EW1[KPAD * NH];            // [vocab-col][16]
__device__ float g_S[KSPLIT * 17 * B_ROWS];   // 8 partials x (16 sums + count)

// ---------------------------------------------------------------------------
// helpers
// ---------------------------------------------------------------------------
__device__ __forceinline__ void fma2(unsigned long long& d, unsigned long long a,
                                     unsigned long long b) {
    asm("fma.rn.f32x2 %0, %1, %2, %0;" : "+l"(d) : "l"(a), "l"(b));
}
__device__ __forceinline__ void add2(unsigned long long& d, unsigned long long a) {
    asm("add.rn.f32x2 %0, %0, %1;" : "+l"(d) : "l"(a));
}
__device__ __forceinline__ unsigned long long pack2(float lo, float hi) {
    unsigned long long r;
    asm("mov.b64 %0, {%1, %2};" : "=l"(r) : "r"(__float_as_uint(lo)), "r"(__float_as_uint(hi)));
    return r;
}
__device__ __forceinline__ void unpack2(unsigned long long v, float& lo, float& hi) {
    unsigned a, b;
    asm("mov.b64 {%0, %1}, %2;" : "=r"(a), "=r"(b) : "l"(v));
    lo = __uint_as_float(a); hi = __uint_as_float(b);
}
__device__ __forceinline__ void cp16(void* s, const void* g) {
    unsigned sa = (unsigned)__cvta_generic_to_shared(s);
    asm volatile("cp.async.cg.shared.global [%0], [%1], 16;" :: "r"(sa), "l"(g));
}
// consume one 4-col group: 8 conflict-free 8B loads + 8 packed f32x2 adds
__device__ __forceinline__ void consume_group(unsigned tbl, uint2 bw, int g,
                                              unsigned long long* acc) {
    const unsigned m = ((bw.x >> (2 * g)) & 3u) | (((bw.y >> (2 * g)) & 3u) << 2);
    const unsigned a = tbl + (g * 16 + m) * EST;
    unsigned long long x0, x1, x2, x3;
    asm("ld.shared.b64 %0, [%1];"     : "=l"(x0) : "r"(a));
    asm("ld.shared.b64 %0, [%1+8];"   : "=l"(x1) : "r"(a));
    asm("ld.shared.b64 %0, [%1+16];"  : "=l"(x2) : "r"(a));
    asm("ld.shared.b64 %0, [%1+24];"  : "=l"(x3) : "r"(a));
    add2(acc[0], x0); add2(acc[1], x1); add2(acc[2], x2); add2(acc[3], x3);
    asm("ld.shared.b64 %0, [%1+32];"  : "=l"(x0) : "r"(a));
    asm("ld.shared.b64 %0, [%1+40];"  : "=l"(x1) : "r"(a));
    asm("ld.shared.b64 %0, [%1+48];"  : "=l"(x2) : "r"(a));
    asm("ld.shared.b64 %0, [%1+56];"  : "=l"(x3) : "r"(a));
    add2(acc[4], x0); add2(acc[5], x1); add2(acc[6], x2); add2(acc[7], x3);
}

// ---------------------------------------------------------------------------
// Kernel 0: g_EW1[c][n] = sum_d embed[c][d] * W1[(2+d)*16+n]   (0 for c>=VOCAB)
// ---------------------------------------------------------------------------
__global__ __launch_bounds__(512) void ew1_kernel(const float* __restrict__ embed,
                                                  const float* __restrict__ W1) {
    __shared__ float sh_emb[32][EMB];
    __shared__ float sh_w1[EMB][NH];
    const int tid = threadIdx.x;
    const int c0  = blockIdx.x * 32;

    for (int i = tid; i < EMB * NH; i += 512)
        sh_w1[i >> 4][i & 15] = W1[NDEM * NH + i];
    for (int i = tid; i < 32 * EMB; i += 512) {
        int r = i >> 7, k = c0 + r;
        sh_emb[r][i & 127] = (k < VOCAB) ? embed[(long long)k * EMB + (i & 127)] : 0.f;
    }
    __syncthreads();

    const int r = tid >> 4, n = tid & 15, k = c0 + r;
    float a0 = 0.f, a1 = 0.f;
    #pragma unroll 16
    for (int d = 0; d < EMB; d += 2) {
        a0 += sh_emb[r][d]     * sh_w1[d][n];
        a1 += sh_emb[r][d + 1] * sh_w1[d + 1][n];
    }
    g_EW1[k * NH + n] = (k < VOCAB) ? (a0 + a1) : 0.f;
}

// ---------------------------------------------------------------------------
// Kernel 1: partial S = mask_tile @ EW1 via 4-bit subset-sum table.
//   R15 chassis + (a) packed-f32x2 consume, (b) batch-0-only prefetch:
//     tile start: cp.async next e + issue 8 next-tile row loads (16 regs)
//     build table (loads in flight) -> sync -> ballot batch 0
//     bb=0..3: [issue batch bb+1] consume groups 4bb..4bb+3 [ballot bb+1]
//   Bit layout: col k -> word (k&1), bit (k>>1). Nibble mapping (R9-proven):
//     m = ((bw.x>>2g)&3) | (((bw.y>>2g)&3)<<2)
//     bit0->e[4g], bit1->e[4g+2], bit2->e[4g+1], bit3->e[4g+3]
// ---------------------------------------------------------------------------
__global__ __launch_bounds__(THREADS, 4) void pool_kernel(const float* __restrict__ src) {
    __shared__ __align__(16) float sh_tbl[NG * 16 * (EST / 4)];  // 22.5 KB
    __shared__ __align__(16) float sh_e[2][KT * NH];             // 8 KB
    __shared__ __align__(8)  uint2 sh_bits[2][TM];               // 4 KB

    const int tid  = threadIdx.x;
    const int w    = tid >> 5;
    const int lane = tid & 31;
    const int mtile = blockIdx.x >> 3;           // / KSPLIT
    const int part  = blockIdx.x & (KSPLIT - 1);
    const int row0  = mtile * TM;
    const int kbase = part * KRANGE;
    const float* sb = src + (long long)row0 * SRC_COLS + NDEM;
    const int cl = 2 * lane;                 // lane's (even) col offset in a tile
    const unsigned tbl = (unsigned)__cvta_generic_to_shared(&sh_tbl[0]);

    // this thread's table item: group bg, mask bm
    const int bg = tid >> 4, bm = tid & 15;
    const unsigned long long q0 = pack2((bm & 1) ? 1.f : 0.f, (bm & 1) ? 1.f : 0.f);  // e[4g]
    const unsigned long long q1 = pack2((bm & 2) ? 1.f : 0.f, (bm & 2) ? 1.f : 0.f);  // e[4g+2]
    const unsigned long long q2 = pack2((bm & 4) ? 1.f : 0.f, (bm & 4) ? 1.f : 0.f);  // e[4g+1]
    const unsigned long long q3 = pack2((bm & 8) ? 1.f : 0.f, (bm & 8) ? 1.f : 0.f);  // e[4g+3]
    const unsigned tdst = tbl + (bg * 16 + bm) * EST;

    // ---------------- prologue: stage tile 0 ----------------
    cp16(&sh_e[0][tid * 4], g_EW1 + kbase * NH + tid * 4);
    asm volatile("cp.async.commit_group;");
    {
        const int c = kbase + cl;
        #pragma unroll
        for (int bb = 0; bb < 4; ++bb) {
            float2 v[8];
            #pragma unroll
            for (int j = 0; j < 8; ++j) {
                int row = 32 * w + 8 * bb + j;
                v[j] = (c < VOCAB)
                     ? __ldcs(reinterpret_cast<const float2*>(sb + (long long)row * SRC_COLS + c))
                     : make_float2(0.f, 0.f);
            }
            #pragma unroll
            for (int j = 0; j < 8; ++j) {
                unsigned b0 = __ballot_sync(0xffffffffu, v[j].x != 0.f);
                unsigned b1 = __ballot_sync(0xffffffffu, v[j].y != 0.f);
                if (lane == 0) sh_bits[0][32 * w + 8 * bb + j] = make_uint2(b0, b1);
            }
        }
    }
    asm volatile("cp.async.wait_group 0;" ::: "memory");
    __syncthreads();

    unsigned long long acc[8];
    #pragma unroll
    for (int i = 0; i < 8; ++i) acc[i] = 0ull;
    int cnt = 0;

    // ---------------- main loop ----------------
    for (int t = 0; t < NT; ++t) {
        const int buf = t & 1, nbuf = buf ^ 1;
        const bool stg = (t + 1 < NT);
        const int cnx = kbase + (t + 1) * KT + cl;

        // (1) prefetch next e-tile + issue batch-0 row loads (8 rows, 16 regs)
        if (stg) {
            cp16(&sh_e[nbuf][tid * 4], g_EW1 + (kbase + (t + 1) * KT) * NH + tid * 4);
            asm volatile("cp.async.commit_group;");
        }
        float2 v[8];
        if (stg) {
            #pragma unroll
            for (int j = 0; j < 8; ++j) {
                int row = 32 * w + j;
                v[j] = (cnx < VOCAB)
                     ? __ldcs(reinterpret_cast<const float2*>(sb + (long long)row * SRC_COLS + cnx))
                     : make_float2(0.f, 0.f);
            }
        }

        // (2) build subset-sum table from sh_e[buf] (loads in flight)
        {
            const unsigned eb = (unsigned)__cvta_generic_to_shared(&sh_e[buf][0]) + bg * 256;
            #pragma unroll
            for (int i = 0; i < 8; ++i) {
                unsigned long long e0, e1, e2, e3, s = 0ull;
                asm("ld.shared.b64 %0, [%1];"     : "=l"(e0) : "r"(eb + i * 8));
                asm("ld.shared.b64 %0, [%1+64];"  : "=l"(e1) : "r"(eb + i * 8));
                asm("ld.shared.b64 %0, [%1+128];" : "=l"(e2) : "r"(eb + i * 8));
                asm("ld.shared.b64 %0, [%1+192];" : "=l"(e3) : "r"(eb + i * 8));
                fma2(s, e0, q0);   // col 4g
                fma2(s, e2, q1);   // col 4g+2
                fma2(s, e1, q2);   // col 4g+1
                fma2(s, e3, q3);   // col 4g+3
                asm volatile("st.shared.b64 [%0], %1;" :: "r"(tdst + i * 8), "l"(s));
            }
        }
        __syncthreads();   // table ready

        const uint2 bw = sh_bits[buf][tid];
        cnt += __popc(bw.x) + __popc(bw.y);

        // (3) ballot batch 0 (its loads covered by build+sync)
        if (stg) {
            #pragma unroll
            for (int j = 0; j < 8; ++j) {
                unsigned p0 = __ballot_sync(0xffffffffu, v[j].x != 0.f);
                unsigned p1 = __ballot_sync(0xffffffffu, v[j].y != 0.f);
                if (lane == 0) sh_bits[nbuf][32 * w + j] = make_uint2(p0, p1);
            }
        }

        // (4) bb loop: issue batch bb+1, consume 4 groups, ballot batch bb+1
        #pragma unroll
        for (int bb = 0; bb < 4; ++bb) {
            if (stg && bb < 3) {
                #pragma unroll
                for (int j = 0; j < 8; ++j) {
                    int row = 32 * w + 8 * (bb + 1) + j;
                    v[j] = (cnx < VOCAB)
                         ? __ldcs(reinterpret_cast<const float2*>(sb + (long long)row * SRC_COLS + cnx))
                         : make_float2(0.f, 0.f);
                }
            }
            #pragma unroll
            for (int gg = 0; gg < 4; ++gg)
                consume_group(tbl, bw, 4 * bb + gg, acc);
            if (stg && bb < 3) {
                #pragma unroll
                for (int j = 0; j < 8; ++j) {
                    unsigned p0 = __ballot_sync(0xffffffffu, v[j].x != 0.f);
                    unsigned p1 = __ballot_sync(0xffffffffu, v[j].y != 0.f);
                    if (lane == 0) sh_bits[nbuf][32 * w + 8 * (bb + 1) + j] = make_uint2(p0, p1);
                }
            }
        }
        if (stg) asm volatile("cp.async.wait_group 0;" ::: "memory");
        __syncthreads();   // bits[nbuf] + e[nbuf] ready; table free to rebuild
    }

    // ---------------- write partials (column-major, coalesced) ----------------
    const int rg = row0 + tid;
    #pragma unroll
    for (int i = 0; i < 8; ++i) {
        float lo, hi;
        unpack2(acc[i], lo, hi);
        g_S[(part * 17 + 2 * i + 0) * B_ROWS + rg] = lo;
        g_S[(part * 17 + 2 * i + 1) * B_ROWS + rg] = hi;
    }
    g_S[(part * 17 + 16) * B_ROWS + rg] = (float)cnt;
}

// ---------------------------------------------------------------------------
// Kernel 2: reduce K-split partials + MLP epilogue
// ---------------------------------------------------------------------------
__global__ void mlp_kernel(const float* __restrict__ src, const float* __restrict__ W1,
                           const float* __restrict__ b1, const float* __restrict__ W2,
                           const float* __restrict__ b2, float* __restrict__ out) {
    int r = blockIdx.x * blockDim.x + threadIdx.x;
    if (r >= B_ROWS) return;

    float s[17];
    #pragma unroll
    for (int n = 0; n < 17; ++n) s[n] = 0.f;
    #pragma unroll
    for (int p = 0; p < KSPLIT; ++p)
        #pragma unroll
        for (int n = 0; n < 17; ++n)
            s[n] += g_S[(p * 17 + n) * B_ROWS + r];

    const float inv = 1.f / s[16];
    const float d0 = src[(long long)r * SRC_COLS + 0];
    const float d1 = src[(long long)r * SRC_COLS + 1];

    float o0 = b2[0], o1 = b2[1];
    #pragma unroll
    for (int j = 0; j < NH; ++j) {
        float z = d0 * W1[j] + d1 * W1[NH + j] + s[j] * inv + b1[j];
        float h = tanhf(z);
        o0 += h * W2[2 * j + 0];
        o1 += h * W2[2 * j + 1];
    }
    out[2 * r + 0] = o0;
    out[2 * r + 1] = o1;
}

// ---------------------------------------------------------------------------
// Launch
// ---------------------------------------------------------------------------
extern "C" void kernel_launch(void* const* d_in, const int* in_sizes, int n_in,
                              void* d_out, int out_size) {
    int iSrc = 0, iEmb = 1, iW1 = 2, iB1 = 3, iW2 = 4, iB2 = 5;
    for (int i = 0; i < n_in; ++i) {
        int s = in_sizes[i];
        if      (s == B_ROWS * SRC_COLS)  iSrc = i;
        else if (s == VOCAB * EMB)        iEmb = i;
        else if (s == (NDEM + EMB) * NH)  iW1  = i;
        else if (s == NH)                 iB1  = i;
        else if (s == NH * 2)             iW2  = i;
        else if (s == 2)                  iB2  = i;
    }
    const float* src   = (const float*)d_in[iSrc];
    const float* embed = (const float*)d_in[iEmb];
    const float* W1    = (const float*)d_in[iW1];
    const float* b1    = (const float*)d_in[iB1];
    const float* W2    = (const float*)d_in[iW2];
    const float* b2    = (const float*)d_in[iB2];
    float* out = (float*)d_out;

    ew1_kernel<<<KPAD / 32, 512>>>(embed, W1);
    pool_kernel<<<NCTA, THREADS>>>(src);
    mlp_kernel<<<(B_ROWS + 255) / 256, 256>>>(src, W1, b1, W2, b2, out);
}